// round 16
// baseline (speedup 1.0000x reference)
#include <cuda_runtime.h>
#include <cuda_bf16.h>
#include <cstdint>
#include <float.h>

// Problem constants
#define NROI   256
#define FH     100
#define FW     50
#define FHW    5000
#define POOL   7
#define KFC    50176               // 1024 * 49
#define NFC    1024
#define NCLS   21
#define NCHUNK 784                 // KFC / 64

// GEMM decomposition: CTA tile 128x128, K-chunk 64, split-K 9
#define SPLITK     9
#define CHUNK_BASE 87              // 784 / 9
#define CHUNK_REM  1               // 784 % 9

// smem tile layout: 4 tiles (Ah,Al,Bh,Bl) of 16KB, double buffered
#define TBYTES   16384
#define BUFBYTES (4 * TBYTES)      // 65536
#define SMEM_DYN (1024 + 2 * BUFBYTES)   // 132096

// Tiled+swizzled global operand layouts (16B units):
//  A: [chunk 784][mblock 2][16KB tile]   tile row = roi&127, cols = k in chunk
//  B: [nblock 8][chunk 784][16KB tile]   tile row = n&127
__device__ uint4 g_a_hi[(size_t)NCHUNK * 2 * 1024];
__device__ uint4 g_a_lo[(size_t)NCHUNK * 2 * 1024];
__device__ uint4 g_b_hi[(size_t)8 * NCHUNK * 1024];
__device__ uint4 g_b_lo[(size_t)8 * NCHUNK * 1024];
__device__ float g_partial[(size_t)SPLITK * NROI * NFC];

// ---------------------------------------------------------------------------
// Portable PTX helpers (sm_90-base or older; nothing arch-suffix-gated)
// ---------------------------------------------------------------------------
__device__ __forceinline__ uint32_t cvta_smem(const void* p) {
    uint32_t a;
    asm("{ .reg .u64 t; cvta.to.shared.u64 t, %1; cvt.u32.u64 %0, t; }"
        : "=r"(a) : "l"(p));
    return a;
}
__device__ __forceinline__ void mbar_init(uint32_t addr, uint32_t cnt) {
    asm volatile("mbarrier.init.shared.b64 [%0], %1;" :: "r"(addr), "r"(cnt) : "memory");
}
__device__ __forceinline__ void mbar_expect_tx(uint32_t addr, uint32_t bytes) {
    asm volatile("mbarrier.arrive.expect_tx.shared.b64 _, [%0], %1;"
                 :: "r"(addr), "r"(bytes) : "memory");
}
__device__ __forceinline__ void mbar_wait(uint32_t addr, uint32_t parity) {
    asm volatile("{\n\t.reg .pred P;\n\t"
                 "WL_%=:\n\t"
                 "mbarrier.try_wait.parity.acquire.cta.shared::cta.b64 P, [%0], %1, 0x989680;\n\t"
                 "@P bra.uni WD_%=;\n\t"
                 "bra.uni WL_%=;\n\t"
                 "WD_%=:\n\t}"
                 :: "r"(addr), "r"(parity) : "memory");
}
// 1D bulk async copy global->shared with mbarrier completion (sm_90 base PTX)
__device__ __forceinline__ void bulk_g2s(uint32_t dst, const void* src, uint32_t bytes,
                                         uint32_t mbar) {
    asm volatile("cp.async.bulk.shared::cluster.global.mbarrier::complete_tx::bytes "
                 "[%0], [%1], %2, [%3];"
                 :: "r"(dst), "l"(src), "r"(bytes), "r"(mbar) : "memory");
}
__device__ __forceinline__ void ldm_x4(uint32_t* r, uint32_t a) {
    asm volatile("ldmatrix.sync.aligned.m8n8.x4.shared.b16 {%0,%1,%2,%3}, [%4];"
                 : "=r"(r[0]), "=r"(r[1]), "=r"(r[2]), "=r"(r[3]) : "r"(a));
}
__device__ __forceinline__ void ldm_x2(uint32_t* r, uint32_t a) {
    asm volatile("ldmatrix.sync.aligned.m8n8.x2.shared.b16 {%0,%1}, [%2];"
                 : "=r"(r[0]), "=r"(r[1]) : "r"(a));
}
__device__ __forceinline__ void mma_bf16(float* c, const uint32_t* a, const uint32_t* b) {
    asm volatile("mma.sync.aligned.m16n8k16.row.col.f32.bf16.bf16.f32 "
                 "{%0,%1,%2,%3}, {%4,%5,%6,%7}, {%8,%9}, {%0,%1,%2,%3};"
                 : "+f"(c[0]), "+f"(c[1]), "+f"(c[2]), "+f"(c[3])
                 : "r"(a[0]), "r"(a[1]), "r"(a[2]), "r"(a[3]), "r"(b[0]), "r"(b[1]));
}
struct alignas(16) bf16x8 { __nv_bfloat162 v[4]; };
__device__ __forceinline__ void split8(const float* f, bf16x8& hi, bf16x8& lo) {
#pragma unroll
    for (int j = 0; j < 4; j++) {
        __nv_bfloat16 h0 = __float2bfloat16_rn(f[2 * j]);
        __nv_bfloat16 h1 = __float2bfloat16_rn(f[2 * j + 1]);
        __nv_bfloat16 l0 = __float2bfloat16_rn(f[2 * j]     - __bfloat162float(h0));
        __nv_bfloat16 l1 = __float2bfloat16_rn(f[2 * j + 1] - __bfloat162float(h1));
        hi.v[j] = __nv_bfloat162{h0, h1};
        lo.v[j] = __nv_bfloat162{l0, l1};
    }
}
__device__ __forceinline__ uint32_t sw128(uint32_t off) {
    return off ^ ((off >> 3) & 0x70);
}

// ---------------------------------------------------------------------------
// Kernel 1: ROI adaptive max-pool 7x7 -> A tiles (hi/lo, tiled-SW128 global).
// rois = max(proposals,0) // 16 ; reference maps h<-x (H=100), w<-y (W=50).
// Each thread computes 8 consecutive k outputs -> one 16B hi + one 16B lo store.
// ---------------------------------------------------------------------------
__global__ __launch_bounds__(512) void roi_pool_kernel(const float* __restrict__ fm,
                                                       const int* __restrict__ prop) {
    int roi = blockIdx.x;
    int4 p = *(const int4*)(prop + roi * 4);
    int h0 = max(p.x, 0) >> 4;
    int w0 = max(p.y, 0) >> 4;
    int h1 = max(p.z, 0) >> 4;
    int w1 = max(p.w, 0) >> 4;
    int sh = h1 - h0 + 1;
    int sw = w1 - w0 + 1;

    int hs[POOL], he[POOL], ws[POOL], we[POOL];
#pragma unroll
    for (int i = 0; i < POOL; i++) {
        hs[i] = h0 + (i * sh) / POOL;
        he[i] = h0 + ((i + 1) * sh + POOL - 1) / POOL;   // ceil
        ws[i] = w0 + (i * sw) / POOL;
        we[i] = w0 + ((i + 1) * sw + POOL - 1) / POOL;
    }

    int mb  = roi >> 7;
    int row = roi & 127;
    for (int base = threadIdx.x; base < KFC / 8; base += blockDim.x) {
        int k0 = base * 8;
        float f[8];
#pragma unroll
        for (int j = 0; j < 8; j++) {
            int idx = k0 + j;
            int c  = idx / 49;
            int b  = idx - c * 49;
            int ph = b / POOL;
            int pw = b - ph * POOL;
            const float* fb = fm + c * FHW;
            float m = -FLT_MAX;
            for (int h = hs[ph]; h < he[ph]; ++h) {
                const float* r = fb + h * FW;
                for (int w = ws[pw]; w < we[pw]; ++w)
                    m = fmaxf(m, r[w]);
            }
            f[j] = m;
        }
        bf16x8 hi, lo;
        split8(f, hi, lo);
        int chunk = k0 >> 6;
        int slot  = (k0 >> 3) & 7;
        size_t u = (size_t)(chunk * 2 + mb) * 1024 + (sw128(row * 128 + slot * 16) >> 4);
        g_a_hi[u] = *(const uint4*)&hi;
        g_a_lo[u] = *(const uint4*)&lo;
    }
}

// ---------------------------------------------------------------------------
// Kernel 2: fc_w fp32 -> split-bf16 hi/lo, tiled-SW128 global layout.
// ---------------------------------------------------------------------------
__global__ __launch_bounds__(128) void convert_b_kernel(const float* __restrict__ W) {
    int n  = blockIdx.y;
    int t  = blockIdx.x * 128 + threadIdx.x;   // 0..6271 (KFC/8)
    int k0 = t * 8;
    const float* src = W + (size_t)n * KFC + k0;
    float f[8];
    *(float4*)(f + 0) = *(const float4*)(src + 0);
    *(float4*)(f + 4) = *(const float4*)(src + 4);
    bf16x8 hi, lo;
    split8(f, hi, lo);
    int chunk = k0 >> 6;
    int slot  = (k0 >> 3) & 7;
    int nb    = n >> 7;
    int row   = n & 127;
    size_t u = (size_t)(nb * NCHUNK + chunk) * 1024 + (sw128(row * 128 + slot * 16) >> 4);
    g_b_hi[u] = *(const uint4*)&hi;
    g_b_lo[u] = *(const uint4*)&lo;
}

// ---------------------------------------------------------------------------
// Kernel 3: split-bf16 GEMM via mma.sync, 1D-bulk-copy smem fill, split-K.
// Compute path identical to the round-8 PASSING kernel (478us, rel_err 2.2e-5).
// ---------------------------------------------------------------------------
__global__ __launch_bounds__(256) void fc_gemm_kernel() {
    extern __shared__ char smem[];
    uint32_t sb = cvta_smem(smem);
    uint32_t mbar0 = sb;                        // mbarriers at +0, +8
    uint32_t tile0 = (sb + 1023u) & ~1023u;
    if (tile0 == sb) tile0 += 1024;

    int tid  = threadIdx.x;
    int wid  = tid >> 5;
    int lane = tid & 31;
    int wm   = wid >> 2;        // 0..1 : warp row (64 m each)
    int wn   = wid & 3;         // 0..3 : warp col (32 n each)

    int bx = blockIdx.x;        // n block (0..7)
    int by = blockIdx.y;        // m block (0..1)
    int z  = blockIdx.z;
    int nch = CHUNK_BASE + (z < CHUNK_REM ? 1 : 0);
    int kc0 = z * CHUNK_BASE + (z < CHUNK_REM ? z : CHUNK_REM);

    if (tid == 0) {
        mbar_init(mbar0, 1);
        mbar_init(mbar0 + 8, 1);
    }
    __syncthreads();

    float acc[4][4][4];
#pragma unroll
    for (int i = 0; i < 4; i++)
#pragma unroll
        for (int j = 0; j < 4; j++)
#pragma unroll
            for (int q = 0; q < 4; q++) acc[i][j][q] = 0.f;

    // issue chunk kc into buffer buf (4 x 16KB bulk copies, one expect_tx)
    auto issue = [&](int kc, int buf) {
        uint32_t tb = tile0 + buf * BUFBYTES;
        uint32_t mb = mbar0 + buf * 8;
        mbar_expect_tx(mb, BUFBYTES);
        const char* as = (const char*)(g_a_hi + (size_t)(kc * 2 + by) * 1024);
        const char* al = (const char*)(g_a_lo + (size_t)(kc * 2 + by) * 1024);
        const char* bs = (const char*)(g_b_hi + (size_t)(bx * NCHUNK + kc) * 1024);
        const char* bl = (const char*)(g_b_lo + (size_t)(bx * NCHUNK + kc) * 1024);
        bulk_g2s(tb,              as, TBYTES, mb);
        bulk_g2s(tb + TBYTES,     al, TBYTES, mb);
        bulk_g2s(tb + 2 * TBYTES, bs, TBYTES, mb);
        bulk_g2s(tb + 3 * TBYTES, bl, TBYTES, mb);
    };

    if (tid == 0) issue(kc0, 0);

    int laneA_row = lane & 15;
    int laneA_kb  = ((lane >> 4) & 1) << 4;
    int laneB_row = lane & 7;
    int laneB_kb  = ((lane >> 3) & 1) << 4;

    int ph0 = 0, ph1 = 0;

    for (int c = 0; c < nch; ++c) {
        int buf = c & 1;
        uint32_t tb = tile0 + buf * BUFBYTES;

        // issue next chunk into the other buffer (safe: consumed last iter,
        // ordered by the end-of-loop __syncthreads)
        if (tid == 0 && c + 1 < nch) issue(kc0 + c + 1, buf ^ 1);

        // wait for current buffer's fill
        if (buf == 0) { mbar_wait(mbar0,     ph0); ph0 ^= 1; }
        else          { mbar_wait(mbar0 + 8, ph1); ph1 ^= 1; }

        uint32_t tAh = tb, tAl = tb + TBYTES, tBh = tb + 2 * TBYTES, tBl = tb + 3 * TBYTES;
#pragma unroll
        for (int ks = 0; ks < 4; ks++) {
            uint32_t a_h[4][4], a_l[4][4], b_h[4][2], b_l[4][2];
#pragma unroll
            for (int i = 0; i < 4; i++) {
                uint32_t sw = sw128((wm * 64 + i * 16 + laneA_row) * 128 + ks * 32 + laneA_kb);
                ldm_x4(a_h[i], tAh + sw);
                ldm_x4(a_l[i], tAl + sw);
            }
#pragma unroll
            for (int j = 0; j < 4; j++) {
                uint32_t sw = sw128((wn * 32 + j * 8 + laneB_row) * 128 + ks * 32 + laneB_kb);
                ldm_x2(b_h[j], tBh + sw);
                ldm_x2(b_l[j], tBl + sw);
            }
#pragma unroll
            for (int i = 0; i < 4; i++)
#pragma unroll
                for (int j = 0; j < 4; j++) {
                    mma_bf16(acc[i][j], a_h[i], b_h[j]);   // hi*hi
                    mma_bf16(acc[i][j], a_h[i], b_l[j]);   // hi*lo
                    mma_bf16(acc[i][j], a_l[i], b_h[j]);   // lo*hi
                }
        }
        __syncthreads();   // all readers done with buf before it is refilled
    }

    // ---- epilogue: c-frag -> g_partial[z][m][n] ----
    int g   = lane >> 2;
    int tig = lane & 3;
    int m0 = by * 128, n0 = bx * 128;
#pragma unroll
    for (int i = 0; i < 4; i++) {
#pragma unroll
        for (int j = 0; j < 4; j++) {
            int m = m0 + wm * 64 + i * 16 + g;
            int n = n0 + wn * 32 + j * 8 + tig * 2;
            float* P = g_partial + ((size_t)z * NROI + m) * NFC + n;
            *(float2*)P             = make_float2(acc[i][j][0], acc[i][j][1]);
            *(float2*)(P + 8 * NFC) = make_float2(acc[i][j][2], acc[i][j][3]);
        }
    }
}

// ---------------------------------------------------------------------------
// Kernel 4: fused split-K reduce + bias + ReLU + heads (cls, argmax, reg).
// One block per ROI, 256 threads; warps parallelize the class dots.
// ---------------------------------------------------------------------------
__global__ __launch_bounds__(256) void heads_kernel(const float* __restrict__ fcb,
                                                    const float* __restrict__ cls_w,
                                                    const float* __restrict__ cls_b,
                                                    const float* __restrict__ reg_w,
                                                    const float* __restrict__ reg_b,
                                                    float* __restrict__ out) {
    __shared__ float rs[NFC];
    __shared__ float scls[NCLS];
    __shared__ int sbest;

    int roi = blockIdx.x;
    int tid = threadIdx.x;
    int wid = tid >> 5;
    int lane = tid & 31;

    for (int k = tid; k < NFC; k += 256) {
        float s = 0.f;
#pragma unroll
        for (int z = 0; z < SPLITK; z++)
            s += g_partial[((size_t)z * NROI + roi) * NFC + k];
        rs[k] = fmaxf(s + fcb[k], 0.f);
    }
    __syncthreads();

    for (int cls = wid; cls < NCLS; cls += 8) {
        const float* w = cls_w + (size_t)cls * NFC;
        float a = 0.f;
        for (int k = lane; k < NFC; k += 32)
            a += rs[k] * w[k];
#pragma unroll
        for (int o = 16; o > 0; o >>= 1)
            a += __shfl_down_sync(0xffffffffu, a, o);
        if (lane == 0) {
            a += cls_b[cls];
            scls[cls] = a;
            out[roi * NCLS + cls] = a;
        }
    }
    __syncthreads();

    if (tid == 0) {
        int best = 0;
        float bv = scls[0];
        for (int j = 1; j < NCLS; j++)
            if (scls[j] > bv) { bv = scls[j]; best = j; }   // first-max tie-break
        sbest = best;
    }
    __syncthreads();

    if (wid < 4) {
        const float* w = reg_w + (size_t)(sbest * 4 + wid) * NFC;
        float a = 0.f;
        for (int k = lane; k < NFC; k += 32)
            a += rs[k] * w[k];
#pragma unroll
        for (int o = 16; o > 0; o >>= 1)
            a += __shfl_down_sync(0xffffffffu, a, o);
        if (lane == 0)
            out[NROI * NCLS + roi * 4 + wid] = a + reg_b[sbest * 4 + wid];
    }
}

// ---------------------------------------------------------------------------
extern "C" void kernel_launch(void* const* d_in, const int* in_sizes, int n_in,
                              void* d_out, int out_size) {
    const float* fm    = (const float*)d_in[0];
    const int*   prop  = (const int*)  d_in[1];
    const float* fc_w  = (const float*)d_in[2];
    const float* fc_b  = (const float*)d_in[3];
    const float* cls_w = (const float*)d_in[4];
    const float* cls_b = (const float*)d_in[5];
    const float* reg_w = (const float*)d_in[6];
    const float* reg_b = (const float*)d_in[7];
    float* out = (float*)d_out;

    cudaFuncSetAttribute(fc_gemm_kernel,
                         cudaFuncAttributeMaxDynamicSharedMemorySize, SMEM_DYN);

    roi_pool_kernel<<<NROI, 512>>>(fm, prop);
    convert_b_kernel<<<dim3(49, NFC), 128>>>(fc_w);       // 49*128 = 6272 = KFC/8
    fc_gemm_kernel<<<dim3(8, 2, SPLITK), 256, SMEM_DYN>>>();
    heads_kernel<<<NROI, 256>>>(fc_b, cls_w, cls_b, reg_w, reg_b, out);
}

// round 17
// speedup vs baseline: 1.0282x; 1.0282x over previous
#include <cuda_runtime.h>
#include <cuda_bf16.h>
#include <cstdint>
#include <float.h>

// Problem constants
#define NROI   256
#define FH     100
#define FW     50
#define FHW    5000
#define POOL   7
#define KFC    50176               // 1024 * 49
#define NFC    1024
#define NCLS   21
#define NCHUNK 784                 // KFC / 64

// GEMM decomposition: CTA tile 128x128, K-chunk 64, split-K 9
#define SPLITK     9
#define CHUNK_BASE 87              // 784 / 9
#define CHUNK_REM  1               // 784 % 9

// smem tile layout: 4 tiles (Ah,Al,Bh,Bl) of 16KB, double buffered
#define TBYTES   16384
#define BUFBYTES (4 * TBYTES)      // 65536
#define SMEM_DYN (1024 + 2 * BUFBYTES)   // 132096

// Tiled+swizzled global A layout (16B units):
//  A: [chunk 784][mblock 2][16KB tile]   tile row = roi&127, cols = k in chunk
__device__ uint4 g_a_hi[(size_t)NCHUNK * 2 * 1024];
__device__ uint4 g_a_lo[(size_t)NCHUNK * 2 * 1024];
__device__ float g_partial[(size_t)SPLITK * NROI * NFC];

// ---------------------------------------------------------------------------
// Portable PTX helpers (sm_90-base or older; nothing arch-suffix-gated)
// ---------------------------------------------------------------------------
__device__ __forceinline__ uint32_t cvta_smem(const void* p) {
    uint32_t a;
    asm("{ .reg .u64 t; cvta.to.shared.u64 t, %1; cvt.u32.u64 %0, t; }"
        : "=r"(a) : "l"(p));
    return a;
}
__device__ __forceinline__ void mbar_init(uint32_t addr, uint32_t cnt) {
    asm volatile("mbarrier.init.shared.b64 [%0], %1;" :: "r"(addr), "r"(cnt) : "memory");
}
__device__ __forceinline__ void mbar_expect_tx(uint32_t addr, uint32_t bytes) {
    asm volatile("mbarrier.arrive.expect_tx.shared.b64 _, [%0], %1;"
                 :: "r"(addr), "r"(bytes) : "memory");
}
__device__ __forceinline__ void mbar_wait(uint32_t addr, uint32_t parity) {
    asm volatile("{\n\t.reg .pred P;\n\t"
                 "WL_%=:\n\t"
                 "mbarrier.try_wait.parity.acquire.cta.shared::cta.b64 P, [%0], %1, 0x989680;\n\t"
                 "@P bra.uni WD_%=;\n\t"
                 "bra.uni WL_%=;\n\t"
                 "WD_%=:\n\t}"
                 :: "r"(addr), "r"(parity) : "memory");
}
// 1D bulk async copy global->shared with mbarrier completion (validated R16)
__device__ __forceinline__ void bulk_g2s(uint32_t dst, const void* src, uint32_t bytes,
                                         uint32_t mbar) {
    asm volatile("cp.async.bulk.shared::cluster.global.mbarrier::complete_tx::bytes "
                 "[%0], [%1], %2, [%3];"
                 :: "r"(dst), "l"(src), "r"(bytes), "r"(mbar) : "memory");
}
__device__ __forceinline__ void ldm_x4(uint32_t* r, uint32_t a) {
    asm volatile("ldmatrix.sync.aligned.m8n8.x4.shared.b16 {%0,%1,%2,%3}, [%4];"
                 : "=r"(r[0]), "=r"(r[1]), "=r"(r[2]), "=r"(r[3]) : "r"(a));
}
__device__ __forceinline__ void ldm_x2(uint32_t* r, uint32_t a) {
    asm volatile("ldmatrix.sync.aligned.m8n8.x2.shared.b16 {%0,%1}, [%2];"
                 : "=r"(r[0]), "=r"(r[1]) : "r"(a));
}
__device__ __forceinline__ void mma_bf16(float* c, const uint32_t* a, const uint32_t* b) {
    asm volatile("mma.sync.aligned.m16n8k16.row.col.f32.bf16.bf16.f32 "
                 "{%0,%1,%2,%3}, {%4,%5,%6,%7}, {%8,%9}, {%0,%1,%2,%3};"
                 : "+f"(c[0]), "+f"(c[1]), "+f"(c[2]), "+f"(c[3])
                 : "r"(a[0]), "r"(a[1]), "r"(a[2]), "r"(a[3]), "r"(b[0]), "r"(b[1]));
}
struct alignas(16) bf16x8 { __nv_bfloat162 v[4]; };
__device__ __forceinline__ void split8(const float* f, bf16x8& hi, bf16x8& lo) {
#pragma unroll
    for (int j = 0; j < 4; j++) {
        __nv_bfloat16 h0 = __float2bfloat16_rn(f[2 * j]);
        __nv_bfloat16 h1 = __float2bfloat16_rn(f[2 * j + 1]);
        __nv_bfloat16 l0 = __float2bfloat16_rn(f[2 * j]     - __bfloat162float(h0));
        __nv_bfloat16 l1 = __float2bfloat16_rn(f[2 * j + 1] - __bfloat162float(h1));
        hi.v[j] = __nv_bfloat162{h0, h1};
        lo.v[j] = __nv_bfloat162{l0, l1};
    }
}
__device__ __forceinline__ uint32_t sw128(uint32_t off) {
    return off ^ ((off >> 3) & 0x70);
}

// ---------------------------------------------------------------------------
// Kernel 1: ROI adaptive max-pool 7x7 -> A tiles (hi/lo, tiled-SW128 global).
// rois = max(proposals,0) // 16 ; reference maps h<-x (H=100), w<-y (W=50).
// (validated Round 16)
// ---------------------------------------------------------------------------
__global__ __launch_bounds__(512) void roi_pool_kernel(const float* __restrict__ fm,
                                                       const int* __restrict__ prop) {
    int roi = blockIdx.x;
    int4 p = *(const int4*)(prop + roi * 4);
    int h0 = max(p.x, 0) >> 4;
    int w0 = max(p.y, 0) >> 4;
    int h1 = max(p.z, 0) >> 4;
    int w1 = max(p.w, 0) >> 4;
    int sh = h1 - h0 + 1;
    int sw = w1 - w0 + 1;

    int hs[POOL], he[POOL], ws[POOL], we[POOL];
#pragma unroll
    for (int i = 0; i < POOL; i++) {
        hs[i] = h0 + (i * sh) / POOL;
        he[i] = h0 + ((i + 1) * sh + POOL - 1) / POOL;   // ceil
        ws[i] = w0 + (i * sw) / POOL;
        we[i] = w0 + ((i + 1) * sw + POOL - 1) / POOL;
    }

    int mb  = roi >> 7;
    int row = roi & 127;
    for (int base = threadIdx.x; base < KFC / 8; base += blockDim.x) {
        int k0 = base * 8;
        float f[8];
#pragma unroll
        for (int j = 0; j < 8; j++) {
            int idx = k0 + j;
            int c  = idx / 49;
            int b  = idx - c * 49;
            int ph = b / POOL;
            int pw = b - ph * POOL;
            const float* fb = fm + c * FHW;
            float m = -FLT_MAX;
            for (int h = hs[ph]; h < he[ph]; ++h) {
                const float* r = fb + h * FW;
                for (int w = ws[pw]; w < we[pw]; ++w)
                    m = fmaxf(m, r[w]);
            }
            f[j] = m;
        }
        bf16x8 hi, lo;
        split8(f, hi, lo);
        int chunk = k0 >> 6;
        int slot  = (k0 >> 3) & 7;
        size_t u = (size_t)(chunk * 2 + mb) * 1024 + (sw128(row * 128 + slot * 16) >> 4);
        g_a_hi[u] = *(const uint4*)&hi;
        g_a_lo[u] = *(const uint4*)&lo;
    }
}

// ---------------------------------------------------------------------------
// Kernel 2: split-bf16 GEMM. A via bulk copies (validated R16 machinery);
// B via fused fp32 LDG -> split -> STS, register-prefetched (validated R8).
// No separate convert pass. Compute path identical to both passing kernels.
// ---------------------------------------------------------------------------
__global__ __launch_bounds__(256) void fc_gemm_kernel(const float* __restrict__ W /*fc_w [NFC,KFC] fp32*/) {
    extern __shared__ char smem[];
    uint32_t sb = cvta_smem(smem);
    uint32_t mbar0 = sb;                        // mbarriers at +0, +8
    uint32_t tile0 = (sb + 1023u) & ~1023u;
    if (tile0 == sb) tile0 += 1024;

    int tid  = threadIdx.x;
    int wid  = tid >> 5;
    int lane = tid & 31;
    int wm   = wid >> 2;        // 0..1 : warp row (64 m each)
    int wn   = wid & 3;         // 0..3 : warp col (32 n each)

    int bx = blockIdx.x;        // n block (0..7)
    int by = blockIdx.y;        // m block (0..1)
    int z  = blockIdx.z;
    int n0 = bx * 128;
    int nch = CHUNK_BASE + (z < CHUNK_REM ? 1 : 0);
    int kc0 = z * CHUNK_BASE + (z < CHUNK_REM ? z : CHUNK_REM);

    if (tid == 0) {
        mbar_init(mbar0, 1);
        mbar_init(mbar0 + 8, 1);
    }
    __syncthreads();

    float acc[4][4][4];
#pragma unroll
    for (int i = 0; i < 4; i++)
#pragma unroll
        for (int j = 0; j < 4; j++)
#pragma unroll
            for (int q = 0; q < 4; q++) acc[i][j][q] = 0.f;

    // issue A tiles of chunk kc into buffer buf (2 x 16KB bulk copies)
    auto issueA = [&](int kc, int buf) {
        uint32_t tb = tile0 + buf * BUFBYTES;
        uint32_t mb = mbar0 + buf * 8;
        mbar_expect_tx(mb, 2 * TBYTES);
        bulk_g2s(tb,          (const char*)(g_a_hi + (size_t)(kc * 2 + by) * 1024), TBYTES, mb);
        bulk_g2s(tb + TBYTES, (const char*)(g_a_lo + (size_t)(kc * 2 + by) * 1024), TBYTES, mb);
    };

    if (tid == 0) issueA(kc0, 0);

    // preload B chunk 0 into buffer 0 (LDG fp32 -> split -> STS)
    {
        size_t k0 = (size_t)kc0 * 64;
#pragma unroll
        for (int i = 0; i < 4; i++) {
            int u = tid + 256 * i;
            int row = u >> 3, slot = u & 7;
            const float* src = W + (size_t)(n0 + row) * KFC + k0 + slot * 8;
            float f[8];
            *(float4*)(f + 0) = *(const float4*)(src + 0);
            *(float4*)(f + 4) = *(const float4*)(src + 4);
            bf16x8 hi, lo;
            split8(f, hi, lo);
            uint32_t sw = sw128(row * 128 + slot * 16);
            *(uint4*)(smem + (tile0 - sb) + 2 * TBYTES + sw) = *(const uint4*)&hi;
            *(uint4*)(smem + (tile0 - sb) + 3 * TBYTES + sw) = *(const uint4*)&lo;
        }
    }
    __syncthreads();   // B(0) visible to all warps

    int laneA_row = lane & 15;
    int laneA_kb  = ((lane >> 4) & 1) << 4;
    int laneB_row = lane & 7;
    int laneB_kb  = ((lane >> 3) & 1) << 4;

    int ph0 = 0, ph1 = 0;

    for (int c = 0; c < nch; ++c) {
        int buf = c & 1;
        uint32_t tb  = tile0 + buf * BUFBYTES;
        uint32_t tbn = tile0 + (buf ^ 1) * BUFBYTES;
        bool havenext = (c + 1 < nch);

        // issue next A tiles (TMA) and prefetch next B fp32 into registers
        if (tid == 0 && havenext) issueA(kc0 + c + 1, buf ^ 1);
        float Bf[4][8];
        if (havenext) {
            size_t k0n = (size_t)(kc0 + c + 1) * 64;
#pragma unroll
            for (int i = 0; i < 4; i++) {
                int u = tid + 256 * i;
                int row = u >> 3, slot = u & 7;
                const float* src = W + (size_t)(n0 + row) * KFC + k0n + slot * 8;
                *(float4*)(Bf[i] + 0) = *(const float4*)(src + 0);
                *(float4*)(Bf[i] + 4) = *(const float4*)(src + 4);
            }
        }

        // wait for this chunk's A tiles
        if (buf == 0) { mbar_wait(mbar0,     ph0); ph0 ^= 1; }
        else          { mbar_wait(mbar0 + 8, ph1); ph1 ^= 1; }

        // compute: 4 k-steps of 16, 3 MMA terms
        uint32_t tAh = tb, tAl = tb + TBYTES, tBh = tb + 2 * TBYTES, tBl = tb + 3 * TBYTES;
#pragma unroll
        for (int ks = 0; ks < 4; ks++) {
            uint32_t a_h[4][4], a_l[4][4], b_h[4][2], b_l[4][2];
#pragma unroll
            for (int i = 0; i < 4; i++) {
                uint32_t sw = sw128((wm * 64 + i * 16 + laneA_row) * 128 + ks * 32 + laneA_kb);
                ldm_x4(a_h[i], tAh + sw);
                ldm_x4(a_l[i], tAl + sw);
            }
#pragma unroll
            for (int j = 0; j < 4; j++) {
                uint32_t sw = sw128((wn * 32 + j * 8 + laneB_row) * 128 + ks * 32 + laneB_kb);
                ldm_x2(b_h[j], tBh + sw);
                ldm_x2(b_l[j], tBl + sw);
            }
#pragma unroll
            for (int i = 0; i < 4; i++)
#pragma unroll
                for (int j = 0; j < 4; j++) {
                    mma_bf16(acc[i][j], a_h[i], b_h[j]);   // hi*hi
                    mma_bf16(acc[i][j], a_h[i], b_l[j]);   // hi*lo
                    mma_bf16(acc[i][j], a_l[i], b_h[j]);   // lo*hi
                }
        }

        // store prefetched B into the other buffer (ALU/STS in MMA's shadow)
        if (havenext) {
#pragma unroll
            for (int i = 0; i < 4; i++) {
                int u = tid + 256 * i;
                int row = u >> 3, slot = u & 7;
                bf16x8 hi, lo;
                split8(Bf[i], hi, lo);
                uint32_t sw = sw128(row * 128 + slot * 16);
                *(uint4*)(smem + (tbn - sb) + 2 * TBYTES + sw) = *(const uint4*)&hi;
                *(uint4*)(smem + (tbn - sb) + 3 * TBYTES + sw) = *(const uint4*)&lo;
            }
        }
        __syncthreads();   // buf's readers done + tbn's B stores visible
    }

    // ---- epilogue: c-frag -> g_partial[z][m][n] ----
    int g   = lane >> 2;
    int tig = lane & 3;
    int m0 = by * 128;
#pragma unroll
    for (int i = 0; i < 4; i++) {
#pragma unroll
        for (int j = 0; j < 4; j++) {
            int m = m0 + wm * 64 + i * 16 + g;
            int n = n0 + wn * 32 + j * 8 + tig * 2;
            float* P = g_partial + ((size_t)z * NROI + m) * NFC + n;
            *(float2*)P             = make_float2(acc[i][j][0], acc[i][j][1]);
            *(float2*)(P + 8 * NFC) = make_float2(acc[i][j][2], acc[i][j][3]);
        }
    }
}

// ---------------------------------------------------------------------------
// Kernel 3: fused split-K reduce + bias + ReLU + heads (validated R16, 13us).
// ---------------------------------------------------------------------------
__global__ __launch_bounds__(256) void heads_kernel(const float* __restrict__ fcb,
                                                    const float* __restrict__ cls_w,
                                                    const float* __restrict__ cls_b,
                                                    const float* __restrict__ reg_w,
                                                    const float* __restrict__ reg_b,
                                                    float* __restrict__ out) {
    __shared__ float rs[NFC];
    __shared__ float scls[NCLS];
    __shared__ int sbest;

    int roi = blockIdx.x;
    int tid = threadIdx.x;
    int wid = tid >> 5;
    int lane = tid & 31;

    for (int k = tid; k < NFC; k += 256) {
        float s = 0.f;
#pragma unroll
        for (int z = 0; z < SPLITK; z++)
            s += g_partial[((size_t)z * NROI + roi) * NFC + k];
        rs[k] = fmaxf(s + fcb[k], 0.f);
    }
    __syncthreads();

    for (int cls = wid; cls < NCLS; cls += 8) {
        const float* w = cls_w + (size_t)cls * NFC;
        float a = 0.f;
        for (int k = lane; k < NFC; k += 32)
            a += rs[k] * w[k];
#pragma unroll
        for (int o = 16; o > 0; o >>= 1)
            a += __shfl_down_sync(0xffffffffu, a, o);
        if (lane == 0) {
            a += cls_b[cls];
            scls[cls] = a;
            out[roi * NCLS + cls] = a;
        }
    }
    __syncthreads();

    if (tid == 0) {
        int best = 0;
        float bv = scls[0];
        for (int j = 1; j < NCLS; j++)
            if (scls[j] > bv) { bv = scls[j]; best = j; }   // first-max tie-break
        sbest = best;
    }
    __syncthreads();

    if (wid < 4) {
        const float* w = reg_w + (size_t)(sbest * 4 + wid) * NFC;
        float a = 0.f;
        for (int k = lane; k < NFC; k += 32)
            a += rs[k] * w[k];
#pragma unroll
        for (int o = 16; o > 0; o >>= 1)
            a += __shfl_down_sync(0xffffffffu, a, o);
        if (lane == 0)
            out[NROI * NCLS + roi * 4 + wid] = a + reg_b[sbest * 4 + wid];
    }
}

// ---------------------------------------------------------------------------
extern "C" void kernel_launch(void* const* d_in, const int* in_sizes, int n_in,
                              void* d_out, int out_size) {
    const float* fm    = (const float*)d_in[0];
    const int*   prop  = (const int*)  d_in[1];
    const float* fc_w  = (const float*)d_in[2];
    const float* fc_b  = (const float*)d_in[3];
    const float* cls_w = (const float*)d_in[4];
    const float* cls_b = (const float*)d_in[5];
    const float* reg_w = (const float*)d_in[6];
    const float* reg_b = (const float*)d_in[7];
    float* out = (float*)d_out;

    cudaFuncSetAttribute(fc_gemm_kernel,
                         cudaFuncAttributeMaxDynamicSharedMemorySize, SMEM_DYN);

    roi_pool_kernel<<<NROI, 512>>>(fm, prop);
    fc_gemm_kernel<<<dim3(8, 2, SPLITK), 256, SMEM_DYN>>>(fc_w);
    heads_kernel<<<NROI, 256>>>(fc_b, cls_w, cls_b, reg_w, reg_b, out);
}